// round 16
// baseline (speedup 1.0000x reference)
#include <cuda_runtime.h>
#include <math.h>
#include <stdint.h>
#include <cuda_bf16.h>

#define NTOK 2048
#define DDIM 1024
#define NEXP 14
#define FDIM 2048
#define NPAIR (2*NTOK)
#define MPAD  (NPAIR + 128)

// ---------------- device scratch ---------------------------------------------
__device__ int   g_count[NEXP];
__device__ int   g_offset[NEXP];
__device__ int   g_pairs[NEXP][NTOK];      // value = token*2 + slot
__device__ int   g_ticket;                 // gate completion ticket (self-resets)
__device__ float g_gatew[NTOK][2];
__device__ __align__(128) float g_xs[MPAD][DDIM];   // gathered x, tf32-rounded
__device__ __align__(128) float g_h1[MPAD][FDIM];   // gemm1 out, tf32-rounded
__device__ __align__(128) float g_out2[NPAIR][DDIM];  // split 0 (+bias)
__device__ __align__(128) float g_out2b[NPAIR][DDIM]; // split 1

// ---------------- helpers -------------------------------------------------------
__device__ __forceinline__ uint32_t to_tf32(float f) {
    uint32_t r;
    asm("cvt.rna.tf32.f32 %0, %1;" : "=r"(r) : "f"(f));
    return r;
}
__device__ __forceinline__ uint32_t smem_u32(const void* p) {
    uint32_t a;
    asm("{ .reg .u64 t; cvta.to.shared.u64 t, %1; cvt.u32.u64 %0, t; }" : "=r"(a) : "l"(p));
    return a;
}

#define MMA_TF32(d, a, b0, b1) \
    asm volatile("mma.sync.aligned.m16n8k8.row.col.f32.tf32.tf32.f32 " \
        "{%0,%1,%2,%3},{%4,%5,%6,%7},{%8,%9},{%0,%1,%2,%3};" \
        : "+f"((d)[0]), "+f"((d)[1]), "+f"((d)[2]), "+f"((d)[3]) \
        : "r"((a)[0]), "r"((a)[1]), "r"((a)[2]), "r"((a)[3]), "r"(b0), "r"(b1))

#define LDSM4(r, addr) \
    asm volatile("ldmatrix.sync.aligned.m8n8.x4.shared.b16 {%0,%1,%2,%3}, [%4];" \
        : "=r"((r)[0]), "=r"((r)[1]), "=r"((r)[2]), "=r"((r)[3]) : "r"(addr))

#define CP16(d, s) \
    asm volatile("cp.async.cg.shared.global [%0], [%1], 16;" :: "r"(d), "l"(s) : "memory")
#define CP_COMMIT() asm volatile("cp.async.commit_group;" ::: "memory")
#define CP_WAIT1()  asm volatile("cp.async.wait_group 1;" ::: "memory")
#define CP_WAIT0()  asm volatile("cp.async.wait_group 0;" ::: "memory")

// ---------------- kernel: zero expert counts ----------------------------------
__global__ void zero_kernel() {
    if (threadIdx.x < NEXP) g_count[threadIdx.x] = 0;
    if (threadIdx.x == NEXP) g_ticket = 0;
}

// ---------------- kernel: gating — smem-staged weights, prefix folded in -------
__global__ void gate_kernel(const float* __restrict__ x,
                            const float* __restrict__ gw) {
    __shared__ float sw[7][DDIM];
    int tid = threadIdx.x;
    int lane = tid & 31, wid = tid >> 5;
    int n = blockIdx.x * 8 + wid;
    const float4* xr = (const float4*)(x + (size_t)n * DDIM);
    float4 xv[8];
    #pragma unroll
    for (int i = 0; i < 8; i++) xv[i] = xr[i * 32 + lane];

    float l0 = -3.0e38f, l1 = -3.0e38f;
    int i0 = 0, i1 = -1;
    #pragma unroll
    for (int pass = 0; pass < 2; pass++) {
        const float4* src = (const float4*)(gw + (size_t)pass * 7 * DDIM);
        float4* dst = (float4*)&sw[0][0];
        #pragma unroll
        for (int it = 0; it < 7; it++) dst[it * 256 + tid] = src[it * 256 + tid];
        __syncthreads();
        for (int ee = 0; ee < 7; ee++) {
            int e = pass * 7 + ee;
            const float4* we = (const float4*)&sw[ee][0];
            float s = 0.f;
            #pragma unroll
            for (int i = 0; i < 8; i++) {
                float4 b = we[i * 32 + lane];
                s += xv[i].x * b.x + xv[i].y * b.y + xv[i].z * b.z + xv[i].w * b.w;
            }
            #pragma unroll
            for (int o = 16; o; o >>= 1) s += __shfl_xor_sync(0xFFFFFFFFu, s, o);
            if (s > l0)      { l1 = l0; i1 = i0; l0 = s; i0 = e; }
            else if (s > l1) { l1 = s;  i1 = e; }
        }
        __syncthreads();
    }
    if (lane == 0) {
        float p1 = expf(l1 - l0);
        float inv = 1.0f / (1.0f + p1);
        g_gatew[n][0] = inv;
        g_gatew[n][1] = p1 * inv;
        int s0 = atomicAdd(&g_count[i0], 1);
        g_pairs[i0][s0] = n * 2 + 0;
        int s1 = atomicAdd(&g_count[i1], 1);
        g_pairs[i1][s1] = n * 2 + 1;
    }
    __syncthreads();
    if (tid == 0) {
        int t = atomicAdd(&g_ticket, 1);
        if (t == gridDim.x - 1) {
            int s = 0;
            for (int e = 0; e < NEXP; e++) { g_offset[e] = s; s += g_count[e]; }
            g_ticket = 0;
        }
    }
}

// ---------------- gather (sort fused): expert-sorted x rows, tf32-rounded -------
__global__ void gather_x(const float* __restrict__ x) {
    int row = blockIdx.x;
    int tid = threadIdx.x;
    float4 v = make_float4(0.f, 0.f, 0.f, 0.f);
    if (row < NPAIR) {
        int e = NEXP - 1;
        #pragma unroll
        for (int k = NEXP - 1; k > 0; k--)
            if (row < g_offset[k]) e = k - 1;
        int pair = g_pairs[e][row - g_offset[e]];
        int tok = pair >> 1;
        v = ((const float4*)(x + (size_t)tok * DDIM))[tid];
    }
    uint4 r = make_uint4(to_tf32(v.x), to_tf32(v.y), to_tf32(v.z), to_tf32(v.w));
    ((uint4*)(g_xs[row]))[tid] = r;
}

// =================================================================================
// TF32 GEMM — 128 threads, 4 warps = 2(m) x 2(n), warp tile 64x64.
//   SA[2]: [128 m][20 u32] (80B stride), A frags via ldmatrix.x4 (proven addrs).
//   SB[3]: [16 k][136 u32] (544B stride), B frags via scalar LDS (8-bank bcast).
//   Loaders: A = 1 row/thread x 4 cp.async(16B); B = 8 thr/row x 4 cp.async.
//   Group order [A(c+1)],[B(c+2)]; wait_group 1 at phase top (A(c),B(c) done,
//   B(c+1) in flight). Ring safety identical to proven R14/R15 schedule.
// =================================================================================
#define SA_BUFB 10240u   // 128*20*4
#define SB_BUFB 8704u    // 16*136*4

// ---------------- GEMM1: h1 = gelu(g_xs @ w1 + b1), tf32-rounded store ----------
__global__ void __launch_bounds__(128, 2)
gemm1_mma(const float* __restrict__ w1,
          const float* __restrict__ b1) {
    int e = blockIdx.z, mt = blockIdx.y;
    int cnt = g_count[e];
    if (mt * 128 >= cnt) return;
    int nt = blockIdx.x;
    int off = g_offset[e];
    int mrow0 = off + mt * 128;

    __shared__ __align__(16) uint32_t SA[2][128][20];
    __shared__ __align__(16) uint32_t SB[3][16][136];

    int tid = threadIdx.x, lane = tid & 31, wid = tid >> 5;
    int wm = wid & 1, wn = wid >> 1;
    int g = lane >> 2, tig = lane & 3;

    // A loader: one row per thread, 64B per chunk
    const float* arow = &g_xs[mrow0 + tid][0];
    uint32_t dA0 = smem_u32(&SA[0][tid][0]);
    // B loader: 8 threads per k-row, 16 floats each
    int bk = tid >> 3, bn = (tid & 7) * 16;
    const float* bsrc = w1 + (size_t)e * DDIM * FDIM + (size_t)bk * FDIM + nt * 128 + bn;
    uint32_t dB0 = smem_u32(&SB[0][bk][bn]);

    auto cpA = [&](int c, int slot) {
        const float* s = arow + (size_t)c * 16;
        uint32_t d = dA0 + slot * SA_BUFB;
        CP16(d, s); CP16(d + 16, s + 4); CP16(d + 32, s + 8); CP16(d + 48, s + 12);
        CP_COMMIT();
    };
    auto cpB = [&](int c, uint32_t d) {
        const float* s = bsrc + (size_t)(c * 16) * FDIM;
        CP16(d, s); CP16(d + 16, s + 4); CP16(d + 32, s + 8); CP16(d + 48, s + 12);
        CP_COMMIT();
    };

    uint32_t aA0 = smem_u32(&SA[0][0][0]) + (wm * 64 + (lane & 15)) * 80 + (lane >> 4) * 16;
    int bn0 = wn * 64 + (lane >> 2);
    int bk0 = lane & 3;

    float acc[4][8][4] = {};

    auto compute = [&](uint32_t aAb, const uint32_t (*sB)[136]) {
        uint32_t bf[8][2][2];
        #pragma unroll
        for (int t = 0; t < 8; t++)
            #pragma unroll
            for (int ks = 0; ks < 2; ks++) {
                bf[t][ks][0] = sB[ks * 8 + bk0][bn0 + t * 8];
                bf[t][ks][1] = sB[ks * 8 + bk0 + 4][bn0 + t * 8];
            }
        #pragma unroll
        for (int ks = 0; ks < 2; ks++)
            #pragma unroll
            for (int i = 0; i < 4; i++) {
                uint32_t a[4];
                LDSM4(a, aAb + ks * 32 + i * 1280);
                #pragma unroll
                for (int t = 0; t < 8; t++)
                    MMA_TF32(acc[i][t], a, bf[t][ks][0], bf[t][ks][1]);
            }
    };

    const int NCH = DDIM / 16;   // 64
    cpA(0, 0);
    cpB(0, dB0);
    cpB(1, dB0 + SB_BUFB);

    uint32_t wrB = dB0 + 2 * SB_BUFB;
    const uint32_t wrBhi = dB0 + 2 * SB_BUFB;
    const uint32_t (*rdB)[136] = SB[0];
    uint32_t aOff = 0;

    for (int c = 0; c < NCH; c++) {
        CP_WAIT1();
        __syncthreads();
        if (c + 1 < NCH) cpA(c + 1, (c + 1) & 1); else CP_COMMIT();
        if (c + 2 < NCH) {
            cpB(c + 2, wrB);
            wrB += SB_BUFB;
            if (wrB > wrBhi) wrB -= 3 * SB_BUFB;
        } else CP_COMMIT();
        compute(aA0 + aOff, rdB);
        aOff ^= SA_BUFB;
        rdB = (rdB == SB[2]) ? SB[0] : rdB + 16;
    }
    CP_WAIT0();

    // epilogue: bias + exact gelu, tf32-rounded store to g_h1
    int lim = cnt - mt * 128; if (lim > 128) lim = 128;
    const float* b1e = b1 + (size_t)e * FDIM + nt * 128;
    #pragma unroll
    for (int i = 0; i < 4; i++) {
        #pragma unroll
        for (int t = 0; t < 8; t++) {
            int col = wn * 64 + t * 8 + tig * 2;
            float bA = b1e[col], bB = b1e[col + 1];
            #pragma unroll
            for (int half = 0; half < 2; half++) {
                int r = wm * 64 + i * 16 + g + half * 8;
                if (r < lim) {
                    float v0 = acc[i][t][half * 2 + 0] + bA;
                    float v1 = acc[i][t][half * 2 + 1] + bB;
                    v0 = 0.5f * v0 * (1.0f + erff(v0 * 0.70710678118654752440f));
                    v1 = 0.5f * v1 * (1.0f + erff(v1 * 0.70710678118654752440f));
                    *(float2*)&g_h1[mrow0 + r][nt * 128 + col] =
                        make_float2(__uint_as_float(to_tf32(v0)),
                                    __uint_as_float(to_tf32(v1)));
                }
            }
        }
    }
}

// ---------------- GEMM2 (split-K x2): out2[s] = h1[:, sK:] @ w2[sK:, :] ----------
__global__ void __launch_bounds__(128, 2)
gemm2_mma(const float* __restrict__ w2,
          const float* __restrict__ b2) {
    int ez = blockIdx.z;
    int e = ez >> 1, sp = ez & 1;
    int mt = blockIdx.y;
    int cnt = g_count[e];
    if (mt * 128 >= cnt) return;
    int nt = blockIdx.x;
    int off = g_offset[e];
    int mrow0 = off + mt * 128;

    __shared__ __align__(16) uint32_t SA[2][128][20];
    __shared__ __align__(16) uint32_t SB[3][16][136];
    __shared__ int pid[128];

    int tid = threadIdx.x, lane = tid & 31, wid = tid >> 5;
    int wm = wid & 1, wn = wid >> 1;
    int g = lane >> 2, tig = lane & 3;

    {
        int m = mt * 128 + tid;
        pid[tid] = (m < cnt) ? g_pairs[e][m] : 0;
    }
    __syncthreads();

    const float* arow = &g_h1[mrow0 + tid][sp * 1024];
    uint32_t dA0 = smem_u32(&SA[0][tid][0]);
    int bk = tid >> 3, bn = (tid & 7) * 16;
    const float* bsrc = w2 + (size_t)e * FDIM * DDIM
                      + (size_t)(sp * 1024 + bk) * DDIM + nt * 128 + bn;
    uint32_t dB0 = smem_u32(&SB[0][bk][bn]);

    auto cpA = [&](int c, int slot) {
        const float* s = arow + (size_t)c * 16;
        uint32_t d = dA0 + slot * SA_BUFB;
        CP16(d, s); CP16(d + 16, s + 4); CP16(d + 32, s + 8); CP16(d + 48, s + 12);
        CP_COMMIT();
    };
    auto cpB = [&](int c, uint32_t d) {
        const float* s = bsrc + (size_t)(c * 16) * DDIM;
        CP16(d, s); CP16(d + 16, s + 4); CP16(d + 32, s + 8); CP16(d + 48, s + 12);
        CP_COMMIT();
    };

    uint32_t aA0 = smem_u32(&SA[0][0][0]) + (wm * 64 + (lane & 15)) * 80 + (lane >> 4) * 16;
    int bn0 = wn * 64 + (lane >> 2);
    int bk0 = lane & 3;

    float acc[4][8][4] = {};

    auto compute = [&](uint32_t aAb, const uint32_t (*sB)[136]) {
        uint32_t bf[8][2][2];
        #pragma unroll
        for (int t = 0; t < 8; t++)
            #pragma unroll
            for (int ks = 0; ks < 2; ks++) {
                bf[t][ks][0] = sB[ks * 8 + bk0][bn0 + t * 8];
                bf[t][ks][1] = sB[ks * 8 + bk0 + 4][bn0 + t * 8];
            }
        #pragma unroll
        for (int ks = 0; ks < 2; ks++)
            #pragma unroll
            for (int i = 0; i < 4; i++) {
                uint32_t a[4];
                LDSM4(a, aAb + ks * 32 + i * 1280);
                #pragma unroll
                for (int t = 0; t < 8; t++)
                    MMA_TF32(acc[i][t], a, bf[t][ks][0], bf[t][ks][1]);
            }
    };

    const int NCH = 1024 / 16;   // 64 per split
    cpA(0, 0);
    cpB(0, dB0);
    cpB(1, dB0 + SB_BUFB);

    uint32_t wrB = dB0 + 2 * SB_BUFB;
    const uint32_t wrBhi = dB0 + 2 * SB_BUFB;
    const uint32_t (*rdB)[136] = SB[0];
    uint32_t aOff = 0;

    for (int c = 0; c < NCH; c++) {
        CP_WAIT1();
        __syncthreads();
        if (c + 1 < NCH) cpA(c + 1, (c + 1) & 1); else CP_COMMIT();
        if (c + 2 < NCH) {
            cpB(c + 2, wrB);
            wrB += SB_BUFB;
            if (wrB > wrBhi) wrB -= 3 * SB_BUFB;
        } else CP_COMMIT();
        compute(aA0 + aOff, rdB);
        aOff ^= SA_BUFB;
        rdB = (rdB == SB[2]) ? SB[0] : rdB + 16;
    }
    CP_WAIT0();

    // epilogue: split 0 adds bias -> g_out2; split 1 raw -> g_out2b
    int lim = cnt - mt * 128; if (lim > 128) lim = 128;
    const float* b2e = b2 + (size_t)e * DDIM + nt * 128;
    #pragma unroll
    for (int i = 0; i < 4; i++) {
        #pragma unroll
        for (int t = 0; t < 8; t++) {
            int col = wn * 64 + t * 8 + tig * 2;
            float bA = sp ? 0.f : b2e[col];
            float bB = sp ? 0.f : b2e[col + 1];
            #pragma unroll
            for (int half = 0; half < 2; half++) {
                int r = wm * 64 + i * 16 + g + half * 8;
                if (r < lim) {
                    int pr = pid[r];
                    float* dst = sp ? &g_out2b[pr][nt * 128 + col]
                                    : &g_out2[pr][nt * 128 + col];
                    *(float2*)dst = make_float2(acc[i][t][half * 2 + 0] + bA,
                                                acc[i][t][half * 2 + 1] + bB);
                }
            }
        }
    }
}

// ---------------- combine: out = clip(x + w0*(o0a+o0b) + w1*(o1a+o1b)) ----------
__global__ void combine_kernel(const float* __restrict__ x,
                               float* __restrict__ out) {
    int i = blockIdx.x * 256 + threadIdx.x;
    int n = i >> 10;
    int d = i & 1023;
    float o0 = g_out2[2 * n + 0][d] + g_out2b[2 * n + 0][d];
    float o1 = g_out2[2 * n + 1][d] + g_out2b[2 * n + 1][d];
    float v = x[i] + g_gatew[n][0] * o0 + g_gatew[n][1] * o1;
    out[i] = fminf(fmaxf(v, -100.0f), 100.0f);
}

// ---------------- launch --------------------------------------------------------
extern "C" void kernel_launch(void* const* d_in, const int* in_sizes, int n_in,
                              void* d_out, int out_size) {
    const float* h      = (const float*)d_in[0];   // (2,1024,1024)
    const float* gate_w = (const float*)d_in[1];   // (14,1024)
    const float* w1     = (const float*)d_in[2];   // (14,1024,2048)
    const float* b1     = (const float*)d_in[3];   // (14,2048)
    const float* w2     = (const float*)d_in[4];   // (14,2048,1024)
    const float* b2     = (const float*)d_in[5];   // (14,1024)
    float* out = (float*)d_out;

    zero_kernel<<<1, 32>>>();
    gate_kernel<<<NTOK / 8, 256>>>(h, gate_w);
    gather_x<<<MPAD, 256>>>(h);
    gemm1_mma<<<dim3(FDIM / 128, NTOK / 128, NEXP), 128>>>(w1, b1);
    gemm2_mma<<<dim3(DDIM / 128, NTOK / 128, NEXP * 2), 128>>>(w2, b2);
    combine_kernel<<<(NTOK * DDIM) / 256, 256>>>(h, out);
}

// round 17
// speedup vs baseline: 1.1277x; 1.1277x over previous
#include <cuda_runtime.h>
#include <math.h>
#include <stdint.h>
#include <cuda_bf16.h>

#define NTOK 2048
#define DDIM 1024
#define NEXP 14
#define FDIM 2048
#define NPAIR (2*NTOK)
#define MPAD  (NPAIR + 128)

// ---------------- device scratch ---------------------------------------------
__device__ int   g_count[NEXP];
__device__ int   g_offset[NEXP];
__device__ int   g_pairs[NEXP][NTOK];      // value = token*2 + slot
__device__ int   g_ticket;                 // gate completion ticket (self-resets)
__device__ int   g_tile;                   // persistent work queue cursor
__device__ int   g_total1, g_totalAll;
__device__ int   g_tbase1[NEXP + 1];       // gemm1 tile base per expert
__device__ int   g_tbase2[NEXP + 1];       // gemm2 tile base per expert
__device__ int   g_blkdone[NEXP * 16];     // per-(e,mt) gemm1 completion count
__device__ float g_gatew[NTOK][2];
__device__ __align__(128) float g_xs[MPAD][DDIM];   // gathered x, tf32-rounded
__device__ __align__(128) float g_h1[MPAD][FDIM];   // gemm1 out, tf32-rounded
__device__ __align__(128) float g_out2[NPAIR][DDIM];  // split 0 (+bias)
__device__ __align__(128) float g_out2b[NPAIR][DDIM]; // split 1

// ---------------- helpers -------------------------------------------------------
__device__ __forceinline__ uint32_t to_tf32(float f) {
    uint32_t r;
    asm("cvt.rna.tf32.f32 %0, %1;" : "=r"(r) : "f"(f));
    return r;
}
__device__ __forceinline__ uint32_t smem_u32(const void* p) {
    uint32_t a;
    asm("{ .reg .u64 t; cvta.to.shared.u64 t, %1; cvt.u32.u64 %0, t; }" : "=r"(a) : "l"(p));
    return a;
}

#define MMA_TF32(d, a, b0, b1) \
    asm volatile("mma.sync.aligned.m16n8k8.row.col.f32.tf32.tf32.f32 " \
        "{%0,%1,%2,%3},{%4,%5,%6,%7},{%8,%9},{%0,%1,%2,%3};" \
        : "+f"((d)[0]), "+f"((d)[1]), "+f"((d)[2]), "+f"((d)[3]) \
        : "r"((a)[0]), "r"((a)[1]), "r"((a)[2]), "r"((a)[3]), "r"(b0), "r"(b1))

#define LDSM4(r, addr) \
    asm volatile("ldmatrix.sync.aligned.m8n8.x4.shared.b16 {%0,%1,%2,%3}, [%4];" \
        : "=r"((r)[0]), "=r"((r)[1]), "=r"((r)[2]), "=r"((r)[3]) : "r"(addr))

#define CP16(d, s) \
    asm volatile("cp.async.cg.shared.global [%0], [%1], 16;" :: "r"(d), "l"(s) : "memory")
#define CP_COMMIT() asm volatile("cp.async.commit_group;" ::: "memory")
#define CP_WAIT1()  asm volatile("cp.async.wait_group 1;" ::: "memory")
#define CP_WAIT0()  asm volatile("cp.async.wait_group 0;" ::: "memory")

#define SA_BUFB 10240u   // 128*20*4
#define SB_BUFB 8704u    // 16*136*4

// ---------------- kernel: zero counters ----------------------------------------
__global__ void zero_kernel() {
    int t = threadIdx.x;
    if (t < NEXP) g_count[t] = 0;
    if (t == NEXP) { g_ticket = 0; g_tile = 0; }
    for (int i = t; i < NEXP * 16; i += 256) g_blkdone[i] = 0;
}

// ---------------- kernel: gating — smem-staged weights, prefix + tile tables ----
__global__ void gate_kernel(const float* __restrict__ x,
                            const float* __restrict__ gw) {
    __shared__ float sw[7][DDIM];
    int tid = threadIdx.x;
    int lane = tid & 31, wid = tid >> 5;
    int n = blockIdx.x * 8 + wid;
    const float4* xr = (const float4*)(x + (size_t)n * DDIM);
    float4 xv[8];
    #pragma unroll
    for (int i = 0; i < 8; i++) xv[i] = xr[i * 32 + lane];

    float l0 = -3.0e38f, l1 = -3.0e38f;
    int i0 = 0, i1 = -1;
    #pragma unroll
    for (int pass = 0; pass < 2; pass++) {
        const float4* src = (const float4*)(gw + (size_t)pass * 7 * DDIM);
        float4* dst = (float4*)&sw[0][0];
        #pragma unroll
        for (int it = 0; it < 7; it++) dst[it * 256 + tid] = src[it * 256 + tid];
        __syncthreads();
        for (int ee = 0; ee < 7; ee++) {
            int e = pass * 7 + ee;
            const float4* we = (const float4*)&sw[ee][0];
            float s = 0.f;
            #pragma unroll
            for (int i = 0; i < 8; i++) {
                float4 b = we[i * 32 + lane];
                s += xv[i].x * b.x + xv[i].y * b.y + xv[i].z * b.z + xv[i].w * b.w;
            }
            #pragma unroll
            for (int o = 16; o; o >>= 1) s += __shfl_xor_sync(0xFFFFFFFFu, s, o);
            if (s > l0)      { l1 = l0; i1 = i0; l0 = s; i0 = e; }
            else if (s > l1) { l1 = s;  i1 = e; }
        }
        __syncthreads();
    }
    if (lane == 0) {
        float p1 = expf(l1 - l0);
        float inv = 1.0f / (1.0f + p1);
        g_gatew[n][0] = inv;
        g_gatew[n][1] = p1 * inv;
        int s0 = atomicAdd(&g_count[i0], 1);
        g_pairs[i0][s0] = n * 2 + 0;
        int s1 = atomicAdd(&g_count[i1], 1);
        g_pairs[i1][s1] = n * 2 + 1;
    }
    __syncthreads();
    if (tid == 0) {
        int t = atomicAdd(&g_ticket, 1);
        if (t == gridDim.x - 1) {
            int s = 0, t1 = 0, t2 = 0;
            for (int e = 0; e < NEXP; e++) {
                g_offset[e] = s; s += g_count[e];
                int mts = (g_count[e] + 127) >> 7;
                g_tbase1[e] = t1; t1 += mts * 16;   // 16 nt tiles per mt
                g_tbase2[e] = t2; t2 += mts * 16;   // 8 nt x 2 sp per mt
            }
            g_tbase1[NEXP] = t1;
            g_tbase2[NEXP] = t2;
            g_total1 = t1;
            g_totalAll = t1 + t2;
            g_ticket = 0;
        }
    }
}

// ---------------- gather (sort fused): expert-sorted x rows, tf32-rounded -------
__global__ void gather_x(const float* __restrict__ x) {
    int row = blockIdx.x;
    int tid = threadIdx.x;
    float4 v = make_float4(0.f, 0.f, 0.f, 0.f);
    if (row < NPAIR) {
        int e = NEXP - 1;
        #pragma unroll
        for (int k = NEXP - 1; k > 0; k--)
            if (row < g_offset[k]) e = k - 1;
        int pair = g_pairs[e][row - g_offset[e]];
        int tok = pair >> 1;
        v = ((const float4*)(x + (size_t)tok * DDIM))[tid];
    }
    uint4 r = make_uint4(to_tf32(v.x), to_tf32(v.y), to_tf32(v.z), to_tf32(v.w));
    ((uint4*)(g_xs[row]))[tid] = r;
}

// =================================================================================
// Persistent fused GEMM kernel. grid=296 (2 CTAs/SM). Ticket queue:
//   tickets [0, total1)         = gemm1 tiles (e, mt, nt)        — R15 body
//   tickets [total1, totalAll)  = gemm2 tiles (e, mt, nt, sp)    — R15 body
// gemm1 tile marks g_blkdone[e*16+mt] (release); gemm2 tile acquires ==16.
// Queue order guarantees all gemm1 tiles claimed before any gemm2 ticket ->
// spin always terminates (claimed tiles finish in finite time).
// =================================================================================
__global__ void __launch_bounds__(256, 2)
moe_gemms(const float* __restrict__ w1, const float* __restrict__ b1,
          const float* __restrict__ w2, const float* __restrict__ b2) {
    __shared__ __align__(16) uint32_t SA[2][128][20];
    __shared__ __align__(16) uint32_t SB[3][16][136];
    __shared__ int pid[128];
    __shared__ int sh_t;

    int tid = threadIdx.x, lane = tid & 31, wid = tid >> 5;
    int wm = wid & 1, wn = wid >> 1;
    int g = lane >> 2, tig = lane & 3;

    uint32_t aA0 = smem_u32(&SA[0][0][0]) + (wm * 64 + (lane & 15)) * 80 + (lane >> 4) * 16;
    int bn0 = wn * 32 + (lane >> 2);
    int bk0 = lane & 3;

    for (;;) {
        __syncthreads();
        if (tid == 0) sh_t = atomicAdd(&g_tile, 1);
        __syncthreads();
        int t = sh_t;
        if (t >= g_totalAll) break;

        float acc[4][4][4] = {};

        auto compute = [&](uint32_t aAb, const uint32_t (*sB)[136]) {
            uint32_t bf[4][2][2];
            #pragma unroll
            for (int tt = 0; tt < 4; tt++)
                #pragma unroll
                for (int ks = 0; ks < 2; ks++) {
                    bf[tt][ks][0] = sB[ks * 8 + bk0][bn0 + tt * 8];
                    bf[tt][ks][1] = sB[ks * 8 + bk0 + 4][bn0 + tt * 8];
                }
            #pragma unroll
            for (int ks = 0; ks < 2; ks++)
                #pragma unroll
                for (int i = 0; i < 4; i++) {
                    uint32_t a[4];
                    LDSM4(a, aAb + ks * 32 + i * 1280);
                    MMA_TF32(acc[i][0], a, bf[0][ks][0], bf[0][ks][1]);
                    MMA_TF32(acc[i][1], a, bf[1][ks][0], bf[1][ks][1]);
                    MMA_TF32(acc[i][2], a, bf[2][ks][0], bf[2][ks][1]);
                    MMA_TF32(acc[i][3], a, bf[3][ks][0], bf[3][ks][1]);
                }
        };

        if (t < g_total1) {
            // ---------------- gemm1 tile ----------------
            int e = 0;
            while (t >= g_tbase1[e + 1]) e++;
            int r = t - g_tbase1[e];
            int mt = r >> 4, nt = r & 15;
            int cnt = g_count[e];
            int mrow0 = g_offset[e] + mt * 128;

            int lm = tid & 127, kh = tid >> 7;
            const float* arow = &g_xs[mrow0 + lm][kh * 8];
            uint32_t dA0 = smem_u32(&SA[0][lm][kh * 8]);
            int bk = tid >> 5, bn = (tid & 31) * 4;
            const float* bsrc = w1 + (size_t)e * DDIM * FDIM + (size_t)bk * FDIM + nt * 128 + bn;
            uint32_t dB0 = smem_u32(&SB[0][bk][bn]);

            auto cpA = [&](int c, int slot) {
                const float* s = arow + (size_t)c * 16;
                uint32_t d = dA0 + slot * SA_BUFB;
                CP16(d, s); CP16(d + 16, s + 4);
                CP_COMMIT();
            };
            auto cpB = [&](int c, uint32_t d) {
                const float* s = bsrc + (size_t)(c * 16) * FDIM;
                CP16(d, s); CP16(d + 8 * 544, s + (size_t)8 * FDIM);
                CP_COMMIT();
            };

            const int NCH = DDIM / 16;   // 64
            cpA(0, 0);
            cpB(0, dB0);
            cpB(1, dB0 + SB_BUFB);
            uint32_t wrB = dB0 + 2 * SB_BUFB;
            const uint32_t wrBhi = dB0 + 2 * SB_BUFB;
            const uint32_t (*rdB)[136] = SB[0];
            uint32_t aOff = 0;

            for (int c = 0; c < NCH; c++) {
                CP_WAIT1();
                __syncthreads();
                if (c + 1 < NCH) cpA(c + 1, (c + 1) & 1); else CP_COMMIT();
                if (c + 2 < NCH) {
                    cpB(c + 2, wrB);
                    wrB += SB_BUFB;
                    if (wrB > wrBhi) wrB -= 3 * SB_BUFB;
                } else CP_COMMIT();
                compute(aA0 + aOff, rdB);
                aOff ^= SA_BUFB;
                rdB = (rdB == SB[2]) ? SB[0] : rdB + 16;
            }
            CP_WAIT0();

            int lim = cnt - mt * 128; if (lim > 128) lim = 128;
            const float* b1e = b1 + (size_t)e * FDIM + nt * 128;
            #pragma unroll
            for (int i = 0; i < 4; i++) {
                #pragma unroll
                for (int tt = 0; tt < 4; tt++) {
                    int col = wn * 32 + tt * 8 + tig * 2;
                    float bA = b1e[col], bB = b1e[col + 1];
                    #pragma unroll
                    for (int half = 0; half < 2; half++) {
                        int rr = wm * 64 + i * 16 + g + half * 8;
                        if (rr < lim) {
                            float v0 = acc[i][tt][half * 2 + 0] + bA;
                            float v1 = acc[i][tt][half * 2 + 1] + bB;
                            v0 = 0.5f * v0 * (1.0f + erff(v0 * 0.70710678118654752440f));
                            v1 = 0.5f * v1 * (1.0f + erff(v1 * 0.70710678118654752440f));
                            *(float2*)&g_h1[mrow0 + rr][nt * 128 + col] =
                                make_float2(__uint_as_float(to_tf32(v0)),
                                            __uint_as_float(to_tf32(v1)));
                        }
                    }
                }
            }
            // release: mark this (e,mt) block's nt-tile done
            __threadfence();
            __syncthreads();
            if (tid == 0) atomicAdd(&g_blkdone[e * 16 + mt], 1);
        } else {
            // ---------------- gemm2 tile ----------------
            int t2 = t - g_total1;
            int e = 0;
            while (t2 >= g_tbase2[e + 1]) e++;
            int r = t2 - g_tbase2[e];
            int mt = r >> 4;
            int q = r & 15;
            int nt = q >> 1, sp = q & 1;
            int cnt = g_count[e];
            int mrow0 = g_offset[e] + mt * 128;

            if (tid < 128) {
                int m = mt * 128 + tid;
                pid[tid] = (m < cnt) ? g_pairs[e][m] : 0;
            }
            // acquire: wait for all 16 gemm1 nt-tiles of (e,mt)
            if (tid == 0) {
                while (atomicAdd(&g_blkdone[e * 16 + mt], 0) != 16) {}
            }
            __syncthreads();
            __threadfence();

            const float* arow = &g_h1[mrow0 + (tid & 127)][sp * 1024 + (tid >> 7) * 8];
            uint32_t dA0 = smem_u32(&SA[0][tid & 127][(tid >> 7) * 8]);
            int bk = tid >> 5, bn = (tid & 31) * 4;
            const float* bsrc = w2 + (size_t)e * FDIM * DDIM
                              + (size_t)(sp * 1024 + bk) * DDIM + nt * 128 + bn;
            uint32_t dB0 = smem_u32(&SB[0][bk][bn]);

            auto cpA = [&](int c, int slot) {
                const float* s = arow + (size_t)c * 16;
                uint32_t d = dA0 + slot * SA_BUFB;
                CP16(d, s); CP16(d + 16, s + 4);
                CP_COMMIT();
            };
            auto cpB = [&](int c, uint32_t d) {
                const float* s = bsrc + (size_t)(c * 16) * DDIM;
                CP16(d, s); CP16(d + 8 * 544, s + (size_t)8 * DDIM);
                CP_COMMIT();
            };

            const int NCH = 1024 / 16;   // 64 per split
            cpA(0, 0);
            cpB(0, dB0);
            cpB(1, dB0 + SB_BUFB);
            uint32_t wrB = dB0 + 2 * SB_BUFB;
            const uint32_t wrBhi = dB0 + 2 * SB_BUFB;
            const uint32_t (*rdB)[136] = SB[0];
            uint32_t aOff = 0;

            for (int c = 0; c < NCH; c++) {
                CP_WAIT1();
                __syncthreads();
                if (c + 1 < NCH) cpA(c + 1, (c + 1) & 1); else CP_COMMIT();
                if (c + 2 < NCH) {
                    cpB(c + 2, wrB);
                    wrB += SB_BUFB;
                    if (wrB > wrBhi) wrB -= 3 * SB_BUFB;
                } else CP_COMMIT();
                compute(aA0 + aOff, rdB);
                aOff ^= SA_BUFB;
                rdB = (rdB == SB[2]) ? SB[0] : rdB + 16;
            }
            CP_WAIT0();

            int lim = cnt - mt * 128; if (lim > 128) lim = 128;
            const float* b2e = b2 + (size_t)e * DDIM + nt * 128;
            #pragma unroll
            for (int i = 0; i < 4; i++) {
                #pragma unroll
                for (int tt = 0; tt < 4; tt++) {
                    int col = wn * 32 + tt * 8 + tig * 2;
                    float bA = sp ? 0.f : b2e[col];
                    float bB = sp ? 0.f : b2e[col + 1];
                    #pragma unroll
                    for (int half = 0; half < 2; half++) {
                        int rr = wm * 64 + i * 16 + g + half * 8;
                        if (rr < lim) {
                            int pr = pid[rr];
                            float* dst = sp ? &g_out2b[pr][nt * 128 + col]
                                            : &g_out2[pr][nt * 128 + col];
                            *(float2*)dst = make_float2(acc[i][tt][half * 2 + 0] + bA,
                                                        acc[i][tt][half * 2 + 1] + bB);
                        }
                    }
                }
            }
        }
    }
}

// ---------------- combine: out = clip(x + w0*(o0a+o0b) + w1*(o1a+o1b)) ----------
__global__ void combine_kernel(const float* __restrict__ x,
                               float* __restrict__ out) {
    int i = blockIdx.x * 256 + threadIdx.x;
    int n = i >> 10;
    int d = i & 1023;
    float o0 = g_out2[2 * n + 0][d] + g_out2b[2 * n + 0][d];
    float o1 = g_out2[2 * n + 1][d] + g_out2b[2 * n + 1][d];
    float v = x[i] + g_gatew[n][0] * o0 + g_gatew[n][1] * o1;
    out[i] = fminf(fmaxf(v, -100.0f), 100.0f);
}

// ---------------- launch --------------------------------------------------------
extern "C" void kernel_launch(void* const* d_in, const int* in_sizes, int n_in,
                              void* d_out, int out_size) {
    const float* h      = (const float*)d_in[0];   // (2,1024,1024)
    const float* gate_w = (const float*)d_in[1];   // (14,1024)
    const float* w1     = (const float*)d_in[2];   // (14,1024,2048)
    const float* b1     = (const float*)d_in[3];   // (14,2048)
    const float* w2     = (const float*)d_in[4];   // (14,2048,1024)
    const float* b2     = (const float*)d_in[5];   // (14,1024)
    float* out = (float*)d_out;

    zero_kernel<<<1, 256>>>();
    gate_kernel<<<NTOK / 8, 256>>>(h, gate_w);
    gather_x<<<MPAD, 256>>>(h);
    moe_gemms<<<296, 256>>>(w1, b1, w2, b2);
    combine_kernel<<<(NTOK * DDIM) / 256, 256>>>(h, out);
}